// round 14
// baseline (speedup 1.0000x reference)
#include <cuda_runtime.h>
#include <cuda_bf16.h>
#include <mma.h>
#include <cstdint>
#include <cmath>

using namespace nvcuda;

#define LQ 2048
#define DIM 1536
#define NH 12
#define HD 128
#define SCALE 0.08838834764831845f   // 128^-0.5
#define NSLICE 3
#define KSLICE (DIM / NSLICE)         // 512  (Eigen gebp kc panel)

// ---------------- scratch (static device globals; no allocation) ----------------
__device__ float g_Qf[NH * LQ * HD];
__device__ float g_Kf[NH * LQ * HD];
__device__ float g_Vf[NH * LQ * HD];
__device__ signed char g_Qi8[NH * LQ * HD];
__device__ signed char g_Ki8[NH * LQ * HD];
__device__ signed char g_Vt8[NH * HD * LQ];   // V int8 transposed [h][d][l]
__device__ int g_Si[(size_t)NH * LQ * LQ];    // raw s32 score dots, 201MB
__device__ float g_M[NH * LQ];
__device__ float g_Z[NH * LQ];
__device__ float g_attnO[LQ * DIM];
__device__ unsigned int g_amax[4];
__device__ unsigned int g_minZ;

__global__ void init_kernel() {
    if (threadIdx.x < 4) g_amax[threadIdx.x] = 0u;
    if (threadIdx.x == 0) g_minZ = 0x7f800000u;  // +inf
}

// ------ fused 3-panel fp32 projections: {Q,K,V} = x @ {Wq,Wk,Wv}^T ---------------
// Bit-identical to R11-R13 (Eigen gebp emulation: 3 serial-ascending 512-panels).
__global__ __launch_bounds__(256) void proj_kernel(
    const float* __restrict__ A, const float* __restrict__ B0,
    const float* __restrict__ B1, const float* __restrict__ B2)
{
    const int K = DIM;
    int mode = blockIdx.z;
    const float* B = (mode == 0) ? B0 : (mode == 1) ? B1 : B2;

    __shared__ float As[8][132];
    __shared__ float Bs[8][68];

    int tid = threadIdx.x;
    int tx = tid & 15, ty = tid >> 4;
    int row0 = blockIdx.y * 128, col0 = blockIdx.x * 64;

    int lr = tid >> 1, lc = (tid & 1) * 4;
    const float* Ap = A + (size_t)(row0 + lr) * K + lc;
    const float* Bp = B + (size_t)(col0 + lr) * K + lc;   // valid for tid<128

    float comb[8][4], acc[8][4];

#pragma unroll 1
    for (int s = 0; s < NSLICE; s++) {
#pragma unroll
        for (int i = 0; i < 8; i++)
#pragma unroll
            for (int j = 0; j < 4; j++) acc[i][j] = 0.f;

        int kbeg = s * KSLICE, kend = kbeg + KSLICE;
        for (int k0 = kbeg; k0 < kend; k0 += 8) {
            __syncthreads();
            {
                float4 a4 = *(const float4*)(Ap + k0);
                As[lc + 0][lr] = a4.x; As[lc + 1][lr] = a4.y;
                As[lc + 2][lr] = a4.z; As[lc + 3][lr] = a4.w;
            }
            if (tid < 128) {
                float4 b4 = *(const float4*)(Bp + k0);
                Bs[lc + 0][lr] = b4.x; Bs[lc + 1][lr] = b4.y;
                Bs[lc + 2][lr] = b4.z; Bs[lc + 3][lr] = b4.w;
            }
            __syncthreads();
#pragma unroll
            for (int kk = 0; kk < 8; kk++) {
                float a[8], b[4];
#pragma unroll
                for (int i = 0; i < 8; i++) a[i] = As[kk][ty * 8 + i];
#pragma unroll
                for (int j = 0; j < 4; j++) b[j] = Bs[kk][tx * 4 + j];
#pragma unroll
                for (int i = 0; i < 8; i++)
#pragma unroll
                    for (int j = 0; j < 4; j++)
                        acc[i][j] = fmaf(a[i], b[j], acc[i][j]);
            }
        }

        if (s == 0) {
#pragma unroll
            for (int i = 0; i < 8; i++)
#pragma unroll
                for (int j = 0; j < 4; j++) comb[i][j] = acc[i][j];
        } else {
#pragma unroll
            for (int i = 0; i < 8; i++)
#pragma unroll
                for (int j = 0; j < 4; j++) comb[i][j] += acc[i][j];
        }
    }

    float* dst = (mode == 0) ? g_Qf : (mode == 1) ? g_Kf : g_Vf;
    float lmax = 0.f;
#pragma unroll
    for (int i = 0; i < 8; i++) {
        int r = row0 + ty * 8 + i;
#pragma unroll
        for (int j = 0; j < 4; j++) {
            int c = col0 + tx * 4 + j;
            float v = comb[i][j];
            int h = c >> 7, d = c & 127;
            dst[((size_t)h * LQ + r) * HD + d] = v;
            lmax = fmaxf(lmax, fabsf(v));
        }
    }
#pragma unroll
    for (int off = 16; off; off >>= 1)
        lmax = fmaxf(lmax, __shfl_xor_sync(0xffffffffu, lmax, off));
    if ((tid & 31) == 0)
        atomicMax(&g_amax[mode], __float_as_uint(lmax));
}

// ------- quantize Q,K to int8 ----------------------------------------------------
__global__ void quant_qk() {
    float sQ = __fdiv_rn(__uint_as_float(g_amax[0]), 127.0f);
    float sK = __fdiv_rn(__uint_as_float(g_amax[1]), 127.0f);
    int idx = blockIdx.x * 256 + threadIdx.x;

    float qi = rintf(__fdiv_rn(g_Qf[idx], sQ));
    qi = fmaxf(-128.f, fminf(127.f, qi));
    g_Qi8[idx] = (signed char)(int)qi;

    float ki = rintf(__fdiv_rn(g_Kf[idx], sK));
    ki = fmaxf(-128.f, fminf(127.f, ki));
    g_Ki8[idx] = (signed char)(int)ki;
}

// ------- quantize V to int8 + transpose to [h][d][l] ------------------------------
__global__ void quant_v() {
    __shared__ signed char t[32][33];
    int h = blockIdx.z;
    int l0 = blockIdx.x * 32, d0 = blockIdx.y * 32;
    int tx = threadIdx.x, ty = threadIdx.y;
    float sV = __fdiv_rn(__uint_as_float(g_amax[2]), 127.0f);
    float v = g_Vf[((size_t)h * LQ + l0 + ty) * HD + d0 + tx];
    float vi = rintf(__fdiv_rn(v, sV));
    vi = fmaxf(-128.f, fminf(127.f, vi));
    t[ty][tx] = (signed char)(int)vi;
    __syncthreads();
    g_Vt8[((size_t)h * HD + d0 + ty) * LQ + l0 + tx] = t[tx][ty];
}

// ------ scores via int8 tensor cores (exact): g_Si = qi @ ki^T --------------------
// grid (LQ/128, LQ/128, NH), 256 threads (8 warps), warp tile 32q x 64k
__global__ __launch_bounds__(256) void score_wmma() {
    __shared__ signed char Qs[128][144];
    __shared__ signed char Ks[128][144];

    int h = blockIdx.z;
    int q0 = blockIdx.y * 128, k0 = blockIdx.x * 128;
    int tid = threadIdx.x, wid = tid >> 5;

    const int4* Qg = (const int4*)(g_Qi8 + ((size_t)h * LQ + q0) * HD);
    const int4* Kg = (const int4*)(g_Ki8 + ((size_t)h * LQ + k0) * HD);
#pragma unroll
    for (int it = 0; it < 4; it++) {
        int idx = it * 256 + tid;
        int r = idx >> 3, sg = idx & 7;
        *(int4*)&Qs[r][sg * 16] = Qg[(size_t)r * 8 + sg];
        *(int4*)&Ks[r][sg * 16] = Kg[(size_t)r * 8 + sg];
    }
    __syncthreads();

    int wq = wid >> 1, wk = wid & 1;   // 4 x 2 warp grid
    wmma::fragment<wmma::accumulator, 16, 16, 16, int> acc[2][4];
#pragma unroll
    for (int i = 0; i < 2; i++)
#pragma unroll
        for (int j = 0; j < 4; j++) wmma::fill_fragment(acc[i][j], 0);

#pragma unroll
    for (int d0 = 0; d0 < 128; d0 += 16) {
        wmma::fragment<wmma::matrix_a, 16, 16, 16, signed char, wmma::row_major> a[2];
        wmma::fragment<wmma::matrix_b, 16, 16, 16, signed char, wmma::col_major> b[4];
#pragma unroll
        for (int i = 0; i < 2; i++)
            wmma::load_matrix_sync(a[i], &Qs[wq * 32 + i * 16][d0], 144);
#pragma unroll
        for (int j = 0; j < 4; j++)
            wmma::load_matrix_sync(b[j], &Ks[wk * 64 + j * 16][d0], 144);
#pragma unroll
        for (int i = 0; i < 2; i++)
#pragma unroll
            for (int j = 0; j < 4; j++)
                wmma::mma_sync(acc[i][j], a[i], b[j], acc[i][j]);
    }

#pragma unroll
    for (int i = 0; i < 2; i++)
#pragma unroll
        for (int j = 0; j < 4; j++)
            wmma::store_matrix_sync(
                g_Si + ((size_t)h * LQ + q0 + wq * 32 + i * 16) * LQ + k0 + wk * 64 + j * 16,
                acc[i][j], LQ, wmma::mem_row_major);
}

// ------ per-row stats: exact max, warp-pattern fp32 Z sum (bit-identical) --------
__global__ __launch_bounds__(256) void rowred_kernel() {
    int gwarp = (blockIdx.x * 256 + threadIdx.x) >> 5;
    int lane = threadIdx.x & 31;
    if (gwarp >= NH * LQ) return;
    const int* srow = g_Si + (size_t)gwarp * LQ;

    float sQ = __fdiv_rn(__uint_as_float(g_amax[0]), 127.0f);
    float sK = __fdiv_rn(__uint_as_float(g_amax[1]), 127.0f);
    float c = (float)((double)sQ * (double)sK * (double)SCALE);

    float m = -3.402823466e+38f;
#pragma unroll 4
    for (int j = 0; j < LQ / 32; j++)
        m = fmaxf(m, (float)srow[lane + 32 * j] * c);
#pragma unroll
    for (int off = 16; off; off >>= 1)
        m = fmaxf(m, __shfl_down_sync(0xffffffffu, m, off));
    m = __shfl_sync(0xffffffffu, m, 0);

    float z = 0.f;
#pragma unroll 4
    for (int j = 0; j < LQ / 32; j++)
        z += expf((float)srow[lane + 32 * j] * c - m);
#pragma unroll
    for (int off = 16; off; off >>= 1)
        z += __shfl_down_sync(0xffffffffu, z, off);

    if (lane == 0) {
        g_M[gwarp] = m;
        g_Z[gwarp] = z;
        atomicMin(&g_minZ, __float_as_uint(z));
    }
}

// ------ PV via int8 tensor cores (exact): probs quantized on the fly --------------
// grid (LQ/64, NH), 256 threads (8 warps 2x4), warp tile 32q x 32d
__global__ __launch_bounds__(256) void pv_wmma() {
    __shared__ signed char Ps[64][128];
    __shared__ int scr[8][256];
    __shared__ float m_s[64], z_s[64];

    int h = blockIdx.y, q0 = blockIdx.x * 64;
    int tid = threadIdx.x, wid = tid >> 5, lane = tid & 31;

    if (tid < 64) {
        m_s[tid] = g_M[h * LQ + q0 + tid];
        z_s[tid] = g_Z[h * LQ + q0 + tid];
    }
    float sQ = __fdiv_rn(__uint_as_float(g_amax[0]), 127.0f);
    float sK = __fdiv_rn(__uint_as_float(g_amax[1]), 127.0f);
    float c = (float)((double)sQ * (double)sK * (double)SCALE);
    float maxp = __fdiv_rn(1.0f, __uint_as_float(g_minZ));
    float sP = __fdiv_rn(maxp, 127.0f);
    float sV = __fdiv_rn(__uint_as_float(g_amax[2]), 127.0f);
    float cPV = (float)((double)sP * (double)sV);
    __syncthreads();

    int wq = wid >> 2, wd = wid & 3;
    wmma::fragment<wmma::accumulator, 16, 16, 16, int> acc[2][2];
#pragma unroll
    for (int i = 0; i < 2; i++)
#pragma unroll
        for (int j = 0; j < 2; j++) wmma::fill_fragment(acc[i][j], 0);

    const signed char* Vb = g_Vt8 + (size_t)h * HD * LQ;

    for (int k0 = 0; k0 < LQ; k0 += 128) {
        __syncthreads();   // previous wmma reads of Ps done
#pragma unroll
        for (int it = 0; it < 8; it++) {
            int idx = it * 256 + tid;
            int q = idx >> 5, kk = (idx & 31) * 4;
            int4 si = *(const int4*)(g_Si + ((size_t)h * LQ + q0 + q) * LQ + k0 + kk);
            float m = m_s[q], z = z_s[q];
            float f0 = fminf(127.f, rintf(__fdiv_rn(__fdiv_rn(expf((float)si.x * c - m), z), sP)));
            float f1 = fminf(127.f, rintf(__fdiv_rn(__fdiv_rn(expf((float)si.y * c - m), z), sP)));
            float f2 = fminf(127.f, rintf(__fdiv_rn(__fdiv_rn(expf((float)si.z * c - m), z), sP)));
            float f3 = fminf(127.f, rintf(__fdiv_rn(__fdiv_rn(expf((float)si.w * c - m), z), sP)));
            *(int*)&Ps[q][kk] = (int)f0 | ((int)f1 << 8) | ((int)f2 << 16) | ((int)f3 << 24);
        }
        __syncthreads();

#pragma unroll
        for (int ks = 0; ks < 128; ks += 16) {
            wmma::fragment<wmma::matrix_a, 16, 16, 16, signed char, wmma::row_major> a[2];
            wmma::fragment<wmma::matrix_b, 16, 16, 16, signed char, wmma::col_major> b[2];
#pragma unroll
            for (int i = 0; i < 2; i++)
                wmma::load_matrix_sync(a[i], &Ps[wq * 32 + i * 16][ks], 128);
#pragma unroll
            for (int j = 0; j < 2; j++)
                wmma::load_matrix_sync(b[j], Vb + (size_t)(wd * 32 + j * 16) * LQ + k0 + ks, LQ);
#pragma unroll
            for (int i = 0; i < 2; i++)
#pragma unroll
                for (int j = 0; j < 2; j++)
                    wmma::mma_sync(acc[i][j], a[i], b[j], acc[i][j]);
        }
    }

    // epilogue: s32 -> float * cPV
#pragma unroll
    for (int i = 0; i < 2; i++)
#pragma unroll
        for (int j = 0; j < 2; j++) {
            wmma::store_matrix_sync(scr[wid], acc[i][j], 16, wmma::mem_row_major);
            __syncwarp();
#pragma unroll
            for (int e = 0; e < 8; e++) {
                int idx = lane * 8 + e;
                int rr = idx >> 4, cc = idx & 15;
                int row = q0 + wq * 32 + i * 16 + rr;
                int col = h * HD + wd * 32 + j * 16 + cc;
                g_attnO[(size_t)row * DIM + col] = (float)scr[wid][idx] * cPV;
            }
            __syncwarp();
        }
}

// ------ output projection via bf16x3 tensor cores: out = attnO @ Wo^T + bias -----
// grid (DIM/128, LQ/128), 256 threads (8 warps 2x4), warp tile 64r x 32c
__device__ __forceinline__ void split3(float x, __nv_bfloat16& h, __nv_bfloat16& m,
                                       __nv_bfloat16& l) {
    h = __float2bfloat16(x);
    float r1 = x - __bfloat162float(h);
    m = __float2bfloat16(r1);
    float r2 = r1 - __bfloat162float(m);
    l = __float2bfloat16(r2);
}

__global__ __launch_bounds__(256) void gemm_wmma(
    const float* __restrict__ B, const float* __restrict__ bias,
    float* __restrict__ Cext)
{
    __shared__ __nv_bfloat16 Ah[128][16], Am[128][16], Al[128][16];
    __shared__ __nv_bfloat16 Bh[128][16], Bm[128][16], Bl[128][16];
    __shared__ float scrf[8][256];

    int tid = threadIdx.x, wid = tid >> 5, lane = tid & 31;
    int row0 = blockIdx.y * 128, col0 = blockIdx.x * 128;
    int wr = wid >> 2, wc = wid & 3;

    wmma::fragment<wmma::accumulator, 16, 16, 16, float> acc[4][2];
#pragma unroll
    for (int i = 0; i < 4; i++)
#pragma unroll
        for (int j = 0; j < 2; j++) wmma::fill_fragment(acc[i][j], 0.f);

    for (int k0 = 0; k0 < DIM; k0 += 16) {
        __syncthreads();
#pragma unroll
        for (int it = 0; it < 2; it++) {
            int idx = it * 256 + tid;
            int r = idx >> 2, sg = (idx & 3) * 4;
            float4 a4 = *(const float4*)(g_attnO + (size_t)(row0 + r) * DIM + k0 + sg);
            split3(a4.x, Ah[r][sg + 0], Am[r][sg + 0], Al[r][sg + 0]);
            split3(a4.y, Ah[r][sg + 1], Am[r][sg + 1], Al[r][sg + 1]);
            split3(a4.z, Ah[r][sg + 2], Am[r][sg + 2], Al[r][sg + 2]);
            split3(a4.w, Ah[r][sg + 3], Am[r][sg + 3], Al[r][sg + 3]);
            float4 b4 = *(const float4*)(B + (size_t)(col0 + r) * DIM + k0 + sg);
            split3(b4.x, Bh[r][sg + 0], Bm[r][sg + 0], Bl[r][sg + 0]);
            split3(b4.y, Bh[r][sg + 1], Bm[r][sg + 1], Bl[r][sg + 1]);
            split3(b4.z, Bh[r][sg + 2], Bm[r][sg + 2], Bl[r][sg + 2]);
            split3(b4.w, Bh[r][sg + 3], Bm[r][sg + 3], Bl[r][sg + 3]);
        }
        __syncthreads();

        wmma::fragment<wmma::matrix_b, 16, 16, 16, __nv_bfloat16, wmma::col_major> bh[2], bm[2], bl[2];
#pragma unroll
        for (int j = 0; j < 2; j++) {
            wmma::load_matrix_sync(bh[j], &Bh[wc * 32 + j * 16][0], 16);
            wmma::load_matrix_sync(bm[j], &Bm[wc * 32 + j * 16][0], 16);
            wmma::load_matrix_sync(bl[j], &Bl[wc * 32 + j * 16][0], 16);
        }
        {
            wmma::fragment<wmma::matrix_a, 16, 16, 16, __nv_bfloat16, wmma::row_major> a[4];
#pragma unroll
            for (int i = 0; i < 4; i++)
                wmma::load_matrix_sync(a[i], &Ah[wr * 64 + i * 16][0], 16);
#pragma unroll
            for (int i = 0; i < 4; i++)
#pragma unroll
                for (int j = 0; j < 2; j++) {
                    wmma::mma_sync(acc[i][j], a[i], bh[j], acc[i][j]);
                    wmma::mma_sync(acc[i][j], a[i], bm[j], acc[i][j]);
                    wmma::mma_sync(acc[i][j], a[i], bl[j], acc[i][j]);
                }
#pragma unroll
            for (int i = 0; i < 4; i++)
                wmma::load_matrix_sync(a[i], &Am[wr * 64 + i * 16][0], 16);
#pragma unroll
            for (int i = 0; i < 4; i++)
#pragma unroll
                for (int j = 0; j < 2; j++) {
                    wmma::mma_sync(acc[i][j], a[i], bh[j], acc[i][j]);
                    wmma::mma_sync(acc[i][j], a[i], bm[j], acc[i][j]);
                }
#pragma unroll
            for (int i = 0; i < 4; i++)
                wmma::load_matrix_sync(a[i], &Al[wr * 64 + i * 16][0], 16);
#pragma unroll
            for (int i = 0; i < 4; i++)
#pragma unroll
                for (int j = 0; j < 2; j++)
                    wmma::mma_sync(acc[i][j], a[i], bh[j], acc[i][j]);
        }
    }

    // epilogue: + bias
#pragma unroll
    for (int i = 0; i < 4; i++)
#pragma unroll
        for (int j = 0; j < 2; j++) {
            wmma::store_matrix_sync((float*)scrf[wid], acc[i][j], 16, wmma::mem_row_major);
            __syncwarp();
#pragma unroll
            for (int e = 0; e < 8; e++) {
                int idx = lane * 8 + e;
                int rr = idx >> 4, cc = idx & 15;
                int row = row0 + wr * 64 + i * 16 + rr;
                int col = col0 + wc * 32 + j * 16 + cc;
                Cext[(size_t)row * DIM + col] = scrf[wid][idx] + bias[col];
            }
            __syncwarp();
        }
}

// ---------------- launch ---------------------------------------------------------
extern "C" void kernel_launch(void* const* d_in, const int* in_sizes, int n_in,
                              void* d_out, int out_size) {
    const float* x  = (const float*)d_in[0];
    const float* Wq = (const float*)d_in[1];
    const float* Wk = (const float*)d_in[2];
    const float* Wv = (const float*)d_in[3];
    const float* Wo = (const float*)d_in[4];
    const float* bo = (const float*)d_in[5];
    float* out = (float*)d_out;

    init_kernel<<<1, 32>>>();

    dim3 gp(DIM / 64, LQ / 128, 3);
    proj_kernel<<<gp, 256>>>(x, Wq, Wk, Wv);

    quant_qk<<<(NH * LQ * HD) / 256, 256>>>();
    quant_v<<<dim3(LQ / 32, HD / 32, NH), dim3(32, 32)>>>();

    score_wmma<<<dim3(LQ / 128, LQ / 128, NH), 256>>>();
    rowred_kernel<<<(NH * LQ * 32 + 255) / 256, 256>>>();
    pv_wmma<<<dim3(LQ / 64, NH), 256>>>();

    gemm_wmma<<<dim3(DIM / 128, LQ / 128), 256>>>(Wo, bo, out);
}

// round 15
// speedup vs baseline: 1.2335x; 1.2335x over previous
#include <cuda_runtime.h>
#include <cuda_bf16.h>
#include <mma.h>
#include <cstdint>
#include <cmath>

using namespace nvcuda;

#define LQ 2048
#define DIM 1536
#define NH 12
#define HD 128
#define SCALE 0.08838834764831845f   // 128^-0.5
#define NSLICE 3
#define KSLICE (DIM / NSLICE)         // 512  (Eigen gebp kc panel)

// ---------------- scratch (static device globals; no allocation) ----------------
__device__ float g_Qf[NH * LQ * HD];
__device__ float g_Kf[NH * LQ * HD];
__device__ float g_Vf[NH * LQ * HD];
__device__ signed char g_Qi8[NH * LQ * HD];
__device__ signed char g_Ki8[NH * LQ * HD];
__device__ signed char g_Vt8[NH * HD * LQ];   // V int8 transposed [h][d][l]
__device__ int g_Si[(size_t)NH * LQ * LQ];    // raw s32 score dots, 201MB
__device__ float g_M[NH * LQ];
__device__ float g_Z[NH * LQ];
__device__ float g_attnO[LQ * DIM];
__device__ __nv_bfloat16 g_Ah[LQ * DIM], g_Al[LQ * DIM];
__device__ __nv_bfloat16 g_Bh[DIM * DIM], g_Bl[DIM * DIM];
__device__ unsigned int g_amax[4];
__device__ unsigned int g_minZ;

__global__ void init_kernel() {
    if (threadIdx.x < 4) g_amax[threadIdx.x] = 0u;
    if (threadIdx.x == 0) g_minZ = 0x7f800000u;  // +inf
}

// ------ fused 3-panel fp32 projections: {Q,K,V} = x @ {Wq,Wk,Wv}^T ---------------
// Bit-identical to R11-R13 (Eigen gebp emulation: 3 serial-ascending 512-panels).
__global__ __launch_bounds__(256) void proj_kernel(
    const float* __restrict__ A, const float* __restrict__ B0,
    const float* __restrict__ B1, const float* __restrict__ B2)
{
    const int K = DIM;
    int mode = blockIdx.z;
    const float* B = (mode == 0) ? B0 : (mode == 1) ? B1 : B2;

    __shared__ float As[8][132];
    __shared__ float Bs[8][68];

    int tid = threadIdx.x;
    int tx = tid & 15, ty = tid >> 4;
    int row0 = blockIdx.y * 128, col0 = blockIdx.x * 64;

    int lr = tid >> 1, lc = (tid & 1) * 4;
    const float* Ap = A + (size_t)(row0 + lr) * K + lc;
    const float* Bp = B + (size_t)(col0 + lr) * K + lc;   // valid for tid<128

    float comb[8][4], acc[8][4];

#pragma unroll 1
    for (int s = 0; s < NSLICE; s++) {
#pragma unroll
        for (int i = 0; i < 8; i++)
#pragma unroll
            for (int j = 0; j < 4; j++) acc[i][j] = 0.f;

        int kbeg = s * KSLICE, kend = kbeg + KSLICE;
        for (int k0 = kbeg; k0 < kend; k0 += 8) {
            __syncthreads();
            {
                float4 a4 = *(const float4*)(Ap + k0);
                As[lc + 0][lr] = a4.x; As[lc + 1][lr] = a4.y;
                As[lc + 2][lr] = a4.z; As[lc + 3][lr] = a4.w;
            }
            if (tid < 128) {
                float4 b4 = *(const float4*)(Bp + k0);
                Bs[lc + 0][lr] = b4.x; Bs[lc + 1][lr] = b4.y;
                Bs[lc + 2][lr] = b4.z; Bs[lc + 3][lr] = b4.w;
            }
            __syncthreads();
#pragma unroll
            for (int kk = 0; kk < 8; kk++) {
                float a[8], b[4];
#pragma unroll
                for (int i = 0; i < 8; i++) a[i] = As[kk][ty * 8 + i];
#pragma unroll
                for (int j = 0; j < 4; j++) b[j] = Bs[kk][tx * 4 + j];
#pragma unroll
                for (int i = 0; i < 8; i++)
#pragma unroll
                    for (int j = 0; j < 4; j++)
                        acc[i][j] = fmaf(a[i], b[j], acc[i][j]);
            }
        }

        if (s == 0) {
#pragma unroll
            for (int i = 0; i < 8; i++)
#pragma unroll
                for (int j = 0; j < 4; j++) comb[i][j] = acc[i][j];
        } else {
#pragma unroll
            for (int i = 0; i < 8; i++)
#pragma unroll
                for (int j = 0; j < 4; j++) comb[i][j] += acc[i][j];
        }
    }

    float* dst = (mode == 0) ? g_Qf : (mode == 1) ? g_Kf : g_Vf;
    float lmax = 0.f;
#pragma unroll
    for (int i = 0; i < 8; i++) {
        int r = row0 + ty * 8 + i;
#pragma unroll
        for (int j = 0; j < 4; j++) {
            int c = col0 + tx * 4 + j;
            float v = comb[i][j];
            int h = c >> 7, d = c & 127;
            dst[((size_t)h * LQ + r) * HD + d] = v;
            lmax = fmaxf(lmax, fabsf(v));
        }
    }
#pragma unroll
    for (int off = 16; off; off >>= 1)
        lmax = fmaxf(lmax, __shfl_xor_sync(0xffffffffu, lmax, off));
    if ((tid & 31) == 0)
        atomicMax(&g_amax[mode], __float_as_uint(lmax));
}

// ------- quantize Q,K to int8 ----------------------------------------------------
__global__ void quant_qk() {
    float sQ = __fdiv_rn(__uint_as_float(g_amax[0]), 127.0f);
    float sK = __fdiv_rn(__uint_as_float(g_amax[1]), 127.0f);
    int idx = blockIdx.x * 256 + threadIdx.x;

    float qi = rintf(__fdiv_rn(g_Qf[idx], sQ));
    qi = fmaxf(-128.f, fminf(127.f, qi));
    g_Qi8[idx] = (signed char)(int)qi;

    float ki = rintf(__fdiv_rn(g_Kf[idx], sK));
    ki = fmaxf(-128.f, fminf(127.f, ki));
    g_Ki8[idx] = (signed char)(int)ki;
}

// ------- quantize V to int8 + transpose to [h][d][l] ------------------------------
__global__ void quant_v() {
    __shared__ signed char t[32][33];
    int h = blockIdx.z;
    int l0 = blockIdx.x * 32, d0 = blockIdx.y * 32;
    int tx = threadIdx.x, ty = threadIdx.y;
    float sV = __fdiv_rn(__uint_as_float(g_amax[2]), 127.0f);
    float v = g_Vf[((size_t)h * LQ + l0 + ty) * HD + d0 + tx];
    float vi = rintf(__fdiv_rn(v, sV));
    vi = fmaxf(-128.f, fminf(127.f, vi));
    t[ty][tx] = (signed char)(int)vi;
    __syncthreads();
    g_Vt8[((size_t)h * HD + d0 + ty) * LQ + l0 + tx] = t[tx][ty];
}

// ------ scores via exact int8 DP4A: g_Si = qi @ ki^T ------------------------------
__global__ __launch_bounds__(256) void score_i8() {
    __shared__ int Qw[32][132];
    __shared__ int Kw[32][132];

    int h = blockIdx.z;
    int q0 = blockIdx.y * 128, k0 = blockIdx.x * 128;
    int tid = threadIdx.x, tx = tid & 15, ty = tid >> 4;

    const uint4* Qg = (const uint4*)(g_Qi8 + ((size_t)h * LQ + q0) * HD);
    const uint4* Kg = (const uint4*)(g_Ki8 + ((size_t)h * LQ + k0) * HD);

#pragma unroll
    for (int it = 0; it < 4; it++) {
        int idx = it * 256 + tid;
        int r = idx >> 3, sg = idx & 7;
        uint4 a = Qg[(size_t)r * 8 + sg];
        Qw[sg * 4 + 0][r] = a.x; Qw[sg * 4 + 1][r] = a.y;
        Qw[sg * 4 + 2][r] = a.z; Qw[sg * 4 + 3][r] = a.w;
        uint4 b = Kg[(size_t)r * 8 + sg];
        Kw[sg * 4 + 0][r] = b.x; Kw[sg * 4 + 1][r] = b.y;
        Kw[sg * 4 + 2][r] = b.z; Kw[sg * 4 + 3][r] = b.w;
    }
    __syncthreads();

    int acc[8][8];
#pragma unroll
    for (int i = 0; i < 8; i++)
#pragma unroll
        for (int j = 0; j < 8; j++) acc[i][j] = 0;

#pragma unroll 4
    for (int w = 0; w < 32; w++) {
        int a[8], b[8];
#pragma unroll
        for (int i = 0; i < 8; i++) a[i] = Qw[w][ty * 8 + i];
#pragma unroll
        for (int j = 0; j < 8; j++) b[j] = Kw[w][tx * 8 + j];
#pragma unroll
        for (int i = 0; i < 8; i++)
#pragma unroll
            for (int j = 0; j < 8; j++)
                acc[i][j] = __dp4a(a[i], b[j], acc[i][j]);
    }

#pragma unroll
    for (int i = 0; i < 8; i++) {
        size_t row = (size_t)h * LQ + q0 + ty * 8 + i;
#pragma unroll
        for (int j = 0; j < 8; j++)
            g_Si[row * LQ + k0 + tx * 8 + j] = acc[i][j];
    }
}

// ------ per-row stats: exact max, warp-pattern fp32 Z sum (bit-identical) --------
__global__ __launch_bounds__(256) void rowred_kernel() {
    int gwarp = (blockIdx.x * 256 + threadIdx.x) >> 5;
    int lane = threadIdx.x & 31;
    if (gwarp >= NH * LQ) return;
    const int* srow = g_Si + (size_t)gwarp * LQ;

    float sQ = __fdiv_rn(__uint_as_float(g_amax[0]), 127.0f);
    float sK = __fdiv_rn(__uint_as_float(g_amax[1]), 127.0f);
    float c = (float)((double)sQ * (double)sK * (double)SCALE);

    float m = -3.402823466e+38f;
#pragma unroll 4
    for (int j = 0; j < LQ / 32; j++)
        m = fmaxf(m, (float)srow[lane + 32 * j] * c);
#pragma unroll
    for (int off = 16; off; off >>= 1)
        m = fmaxf(m, __shfl_down_sync(0xffffffffu, m, off));
    m = __shfl_sync(0xffffffffu, m, 0);

    float z = 0.f;
#pragma unroll 4
    for (int j = 0; j < LQ / 32; j++)
        z += expf((float)srow[lane + 32 * j] * c - m);
#pragma unroll
    for (int off = 16; off; off >>= 1)
        z += __shfl_down_sync(0xffffffffu, z, off);

    if (lane == 0) {
        g_M[gwarp] = m;
        g_Z[gwarp] = z;
        atomicMin(&g_minZ, __float_as_uint(z));
    }
}

// ------ PV via exact int8 DP4A: probs quantized on the fly -----------------------
__global__ __launch_bounds__(256) void pv_i8() {
    __shared__ int Pw[32][68];     // [kw][q]
    __shared__ int Vw[32][132];    // [kw][d]
    __shared__ float m_s[64], z_s[64];

    int h = blockIdx.y, q0 = blockIdx.x * 64;
    int tid = threadIdx.x, tx = tid & 15, ty = tid >> 4;

    if (tid < 64) {
        m_s[tid] = g_M[h * LQ + q0 + tid];
        z_s[tid] = g_Z[h * LQ + q0 + tid];
    }
    float sQ = __fdiv_rn(__uint_as_float(g_amax[0]), 127.0f);
    float sK = __fdiv_rn(__uint_as_float(g_amax[1]), 127.0f);
    float c = (float)((double)sQ * (double)sK * (double)SCALE);
    float maxp = __fdiv_rn(1.0f, __uint_as_float(g_minZ));
    float sP = __fdiv_rn(maxp, 127.0f);
    float sV = __fdiv_rn(__uint_as_float(g_amax[2]), 127.0f);
    float cPV = (float)((double)sP * (double)sV);
    __syncthreads();

    int o[4][8];
#pragma unroll
    for (int i = 0; i < 4; i++)
#pragma unroll
        for (int j = 0; j < 8; j++) o[i][j] = 0;

    const uint4* Vg = (const uint4*)(g_Vt8 + (size_t)h * HD * LQ);

    for (int k0 = 0; k0 < LQ; k0 += 128) {
        __syncthreads();
#pragma unroll
        for (int it = 0; it < 8; it++) {
            int idx = it * 256 + tid;
            int q = idx >> 5, kw = idx & 31;
            int4 si = *(const int4*)(g_Si + ((size_t)h * LQ + q0 + q) * LQ + k0 + kw * 4);
            float m = m_s[q], z = z_s[q];
            float f0 = fminf(127.f, rintf(__fdiv_rn(__fdiv_rn(expf((float)si.x * c - m), z), sP)));
            float f1 = fminf(127.f, rintf(__fdiv_rn(__fdiv_rn(expf((float)si.y * c - m), z), sP)));
            float f2 = fminf(127.f, rintf(__fdiv_rn(__fdiv_rn(expf((float)si.z * c - m), z), sP)));
            float f3 = fminf(127.f, rintf(__fdiv_rn(__fdiv_rn(expf((float)si.w * c - m), z), sP)));
            Pw[kw][q] = (int)f0 | ((int)f1 << 8) | ((int)f2 << 16) | ((int)f3 << 24);
        }
#pragma unroll
        for (int it = 0; it < 4; it++) {
            int idx = it * 256 + tid;
            int d = idx >> 3, sg = idx & 7;
            uint4 v = Vg[(size_t)d * (LQ / 16) + (k0 / 16) + sg];
            Vw[sg * 4 + 0][d] = v.x; Vw[sg * 4 + 1][d] = v.y;
            Vw[sg * 4 + 2][d] = v.z; Vw[sg * 4 + 3][d] = v.w;
        }
        __syncthreads();

#pragma unroll 4
        for (int kw = 0; kw < 32; kw++) {
            int a[4], b[8];
#pragma unroll
            for (int i = 0; i < 4; i++) a[i] = Pw[kw][ty * 4 + i];
#pragma unroll
            for (int j = 0; j < 8; j++) b[j] = Vw[kw][tx * 8 + j];
#pragma unroll
            for (int i = 0; i < 4; i++)
#pragma unroll
                for (int j = 0; j < 8; j++)
                    o[i][j] = __dp4a(a[i], b[j], o[i][j]);
        }
    }

#pragma unroll
    for (int i = 0; i < 4; i++) {
        int row = q0 + ty * 4 + i;
#pragma unroll
        for (int j = 0; j < 8; j++)
            g_attnO[(size_t)row * DIM + h * HD + tx * 8 + j] = (float)o[i][j] * cPV;
    }
}

// ------ bf16 hi/lo split passes ---------------------------------------------------
__global__ void split_wo(const float* __restrict__ W) {
    int i = blockIdx.x * 256 + threadIdx.x;
    float x = W[i];
    __nv_bfloat16 h = __float2bfloat16(x);
    g_Bh[i] = h;
    g_Bl[i] = __float2bfloat16(x - __bfloat162float(h));
}

__global__ void split_ao() {
    int i = blockIdx.x * 256 + threadIdx.x;
    float x = g_attnO[i];
    __nv_bfloat16 h = __float2bfloat16(x);
    g_Ah[i] = h;
    g_Al[i] = __float2bfloat16(x - __bfloat162float(h));
}

// ------ output projection via bf16x2 tensor cores: out = attnO @ Wo^T + bias -----
// Block 128 rows x 64 cols; 8 warps (4 row x 2 col), warp tile 32x32; K-tile 64.
#define GK 64
#define LDA 72
__global__ __launch_bounds__(256) void gemm_bf16(
    const float* __restrict__ bias, float* __restrict__ Cext)
{
    extern __shared__ char smraw[];
    __nv_bfloat16* Ah_s = (__nv_bfloat16*)smraw;                 // [128][72]
    __nv_bfloat16* Al_s = Ah_s + 128 * LDA;
    __nv_bfloat16* Bh_s = Al_s + 128 * LDA;                      // [64][72]
    __nv_bfloat16* Bl_s = Bh_s + 64 * LDA;
    float* scr = (float*)(Bl_s + 64 * LDA);                      // [8][256]

    int tid = threadIdx.x, wid = tid >> 5, lane = tid & 31;
    int row0 = blockIdx.y * 128, col0 = blockIdx.x * 64;
    int wr = wid >> 1, wc = wid & 1;   // 4 x 2 warps, warp tile 32r x 32c

    wmma::fragment<wmma::accumulator, 16, 16, 16, float> acc[2][2];
#pragma unroll
    for (int i = 0; i < 2; i++)
#pragma unroll
        for (int j = 0; j < 2; j++) wmma::fill_fragment(acc[i][j], 0.f);

    for (int k0 = 0; k0 < DIM; k0 += GK) {
        __syncthreads();
        // A tiles: 128 rows x 64 k  (1024 int4 per array)
#pragma unroll
        for (int it = 0; it < 4; it++) {
            int idx = it * 256 + tid;
            int r = idx >> 3, c8 = (idx & 7) * 8;
            *(int4*)&Ah_s[r * LDA + c8] =
                *(const int4*)&g_Ah[(size_t)(row0 + r) * DIM + k0 + c8];
            *(int4*)&Al_s[r * LDA + c8] =
                *(const int4*)&g_Al[(size_t)(row0 + r) * DIM + k0 + c8];
        }
        // B tiles: 64 rows x 64 k  (512 int4 per array)
#pragma unroll
        for (int it = 0; it < 2; it++) {
            int idx = it * 256 + tid;
            int r = idx >> 3, c8 = (idx & 7) * 8;
            *(int4*)&Bh_s[r * LDA + c8] =
                *(const int4*)&g_Bh[(size_t)(col0 + r) * DIM + k0 + c8];
            *(int4*)&Bl_s[r * LDA + c8] =
                *(const int4*)&g_Bl[(size_t)(col0 + r) * DIM + k0 + c8];
        }
        __syncthreads();

#pragma unroll
        for (int ks = 0; ks < GK; ks += 16) {
            wmma::fragment<wmma::matrix_a, 16, 16, 16, __nv_bfloat16, wmma::row_major> a[2];
            wmma::fragment<wmma::matrix_b, 16, 16, 16, __nv_bfloat16, wmma::col_major> bh[2], bl[2];
#pragma unroll
            for (int j = 0; j < 2; j++) {
                wmma::load_matrix_sync(bh[j], &Bh_s[(wc * 32 + j * 16) * LDA + ks], LDA);
                wmma::load_matrix_sync(bl[j], &Bl_s[(wc * 32 + j * 16) * LDA + ks], LDA);
            }
#pragma unroll
            for (int i = 0; i < 2; i++)
                wmma::load_matrix_sync(a[i], &Ah_s[(wr * 32 + i * 16) * LDA + ks], LDA);
#pragma unroll
            for (int i = 0; i < 2; i++)
#pragma unroll
                for (int j = 0; j < 2; j++) {
                    wmma::mma_sync(acc[i][j], a[i], bh[j], acc[i][j]);
                    wmma::mma_sync(acc[i][j], a[i], bl[j], acc[i][j]);
                }
#pragma unroll
            for (int i = 0; i < 2; i++)
                wmma::load_matrix_sync(a[i], &Al_s[(wr * 32 + i * 16) * LDA + ks], LDA);
#pragma unroll
            for (int i = 0; i < 2; i++)
#pragma unroll
                for (int j = 0; j < 2; j++)
                    wmma::mma_sync(acc[i][j], a[i], bh[j], acc[i][j]);
        }
    }

    // epilogue: + bias
#pragma unroll
    for (int i = 0; i < 2; i++)
#pragma unroll
        for (int j = 0; j < 2; j++) {
            wmma::store_matrix_sync(&scr[wid * 256], acc[i][j], 16, wmma::mem_row_major);
            __syncwarp();
#pragma unroll
            for (int e = 0; e < 8; e++) {
                int idx = lane * 8 + e;
                int rr = idx >> 4, cc = idx & 15;
                int row = row0 + wr * 32 + i * 16 + rr;
                int col = col0 + wc * 32 + j * 16 + cc;
                Cext[(size_t)row * DIM + col] = scr[wid * 256 + idx] + bias[col];
            }
            __syncwarp();
        }
}

// ---------------- launch ---------------------------------------------------------
extern "C" void kernel_launch(void* const* d_in, const int* in_sizes, int n_in,
                              void* d_out, int out_size) {
    const float* x  = (const float*)d_in[0];
    const float* Wq = (const float*)d_in[1];
    const float* Wk = (const float*)d_in[2];
    const float* Wv = (const float*)d_in[3];
    const float* Wo = (const float*)d_in[4];
    const float* bo = (const float*)d_in[5];
    float* out = (float*)d_out;

    const int gemm_smem = (2 * 128 * LDA + 2 * 64 * LDA) * 2 + 8 * 256 * 4;
    cudaFuncSetAttribute(gemm_bf16, cudaFuncAttributeMaxDynamicSharedMemorySize,
                         gemm_smem);

    init_kernel<<<1, 32>>>();

    split_wo<<<(DIM * DIM) / 256, 256>>>(Wo);

    dim3 gp(DIM / 64, LQ / 128, 3);
    proj_kernel<<<gp, 256>>>(x, Wq, Wk, Wv);

    quant_qk<<<(NH * LQ * HD) / 256, 256>>>();
    quant_v<<<dim3(LQ / 32, HD / 32, NH), dim3(32, 32)>>>();

    score_i8<<<dim3(LQ / 128, LQ / 128, NH), 256>>>();
    rowred_kernel<<<(NH * LQ * 32 + 255) / 256, 256>>>();
    pv_i8<<<dim3(LQ / 64, NH), 256>>>();

    split_ao<<<(LQ * DIM) / 256, 256>>>();
    gemm_bf16<<<dim3(DIM / 64, LQ / 128), 256, gemm_smem>>>(bo, out);
}